// round 9
// baseline (speedup 1.0000x reference)
#include <cuda_runtime.h>
#include <cstdint>

#define NQ   32
#define KCB  1024
#define CD   8
#define DD   1024
#define TT   4096
#define BB   8

#define KM       4
#define NWARPS   8
#define NTHREADS 256
#define COLS_PB  (KM * NWARPS)          // 32
#define NBLOCKS  ((BB * TT) / COLS_PB)  // 1024

#define QOUT_ELEMS (BB * DD * TT)
#define IDX_ELEMS  (NQ * BB * TT)
#define FULL_OUT   (QOUT_ELEMS + IDX_ELEMS + BB)

// SMEM: W_inT (1024x12 padded), W_out (1024x12), cbn (1024x12), b_out, b_in
#define SMEM_FLOATS (DD*12 + DD*12 + KCB*12 + DD + 8)
#define SMEM_BYTES  (SMEM_FLOATS * 4)

typedef unsigned long long u64t;

// ---- f32x2 packed helpers (FFMA2 path: only reachable via PTX) ----
__device__ __forceinline__ u64t pk2(float a, float b) {
    u64t r; asm("mov.b64 %0,{%1,%2};" : "=l"(r) : "f"(a), "f"(b)); return r;
}
__device__ __forceinline__ float2 upk2(u64t v) {
    float2 r; asm("mov.b64 {%0,%1},%2;" : "=f"(r.x), "=f"(r.y) : "l"(v)); return r;
}
__device__ __forceinline__ void fma2(u64t& d, u64t a, u64t b) {
    asm("fma.rn.f32x2 %0,%1,%2,%0;" : "+l"(d) : "l"(a), "l"(b));
}
__device__ __forceinline__ u64t mul2(u64t a, u64t b) {
    u64t r; asm("mul.rn.f32x2 %0,%1,%2;" : "=l"(r) : "l"(a), "l"(b)); return r;
}
__device__ __forceinline__ u64t add2(u64t a, u64t b) {
    u64t r; asm("add.rn.f32x2 %0,%1,%2;" : "=l"(r) : "l"(a), "l"(b)); return r;
}

// Precomputed scratch (device globals: no allocation allowed)
__device__ float g_winT[NQ * DD * CD];   // [nq][d][c]
__device__ float g_cbn [NQ * KCB * CD];  // normalized codebooks [nq][k][c]
__device__ int   g_len [BB];

// ---------------------------------------------------------------------------
__global__ void rvq_precompute(const float* __restrict__ W_in,
                               const float* __restrict__ cb,
                               const long long* __restrict__ len64,
                               float* __restrict__ out, int out_size) {
    int tid = blockIdx.x * blockDim.x + threadIdx.x;
    int nq  = tid >> 13;
    int rem = tid & 8191;
    int d   = rem >> 3;
    int c   = rem & 7;
    g_winT[tid] = W_in[(nq * CD + c) * DD + d];

    if (tid < NQ * KCB) {
        const float* row = cb + (size_t)tid * CD;
        float v[8], n2 = 0.0f;
#pragma unroll
        for (int i = 0; i < 8; i++) { v[i] = row[i]; n2 = fmaf(v[i], v[i], n2); }
        float s = fmaxf(__fsqrt_rn(n2), 1e-12f);
#pragma unroll
        for (int i = 0; i < 8; i++)
            g_cbn[(size_t)tid * CD + i] = __fdiv_rn(v[i], s);
    }

    if (tid == 0) {
        long long tmp[BB]; bool ok = true;
        for (int i = 0; i < BB; i++) {
            tmp[i] = len64[i];
            if (tmp[i] < 0 || tmp[i] > TT) ok = false;
        }
        if (ok) { for (int i = 0; i < BB; i++) g_len[i] = (int)tmp[i]; }
        else    { const int* l = (const int*)len64;
                  for (int i = 0; i < BB; i++) g_len[i] = l[i]; }
        if (out_size >= FULL_OUT)
            for (int i = 0; i < BB; i++)
                out[QOUT_ELEMS + IDX_ELEMS + i] = (float)g_len[i];
    }
}

// ---------------------------------------------------------------------------
// Fused RVQ (R2 structure): one warp owns 4 columns, residual in registers.
// Partial unrolls bound live ranges -> no register spills.
// ---------------------------------------------------------------------------
__global__ void __launch_bounds__(NTHREADS, 1)
rvq_kernel(const float* __restrict__ z,
           const float* __restrict__ b_in,
           const float* __restrict__ W_out,
           const float* __restrict__ b_out,
           const float* __restrict__ cb,
           float* __restrict__ out, int out_size) {
    extern __shared__ float sm[];
    float* sWinT = sm;                     // [d*12 + c]
    float* sWout = sWinT + DD * 12;
    float* sCbn  = sWout + DD * 12;
    float* sBout = sCbn  + KCB * 12;
    float* sBin  = sBout + DD;

    const int lane = threadIdx.x & 31;
    const int warp = threadIdx.x >> 5;
    const int b    = blockIdx.x >> 7;
    const int t0   = ((blockIdx.x & 127) * COLS_PB) + warp * KM;

    const int len = g_len[b];
    float maskf[KM], nmf[KM];
#pragma unroll
    for (int j = 0; j < KM; j++) {
        maskf[j] = ((t0 + j) < len) ? 1.0f : 0.0f;
        nmf[j]   = -maskf[j];
    }

    // residual = z * mask
    float r[KM][32];
    const float* zbase = z + ((size_t)b * DD) * TT + t0;
#pragma unroll 8
    for (int i = 0; i < 32; i++) {
        int d = lane + 32 * i;
        float4 v = *reinterpret_cast<const float4*>(zbase + (size_t)d * TT);
        r[0][i] = v.x * maskf[0];
        r[1][i] = v.y * maskf[1];
        r[2][i] = v.z * maskf[2];
        r[3][i] = v.w * maskf[3];
    }

    const bool write_idx = (out_size >= QOUT_ELEMS + IDX_ELEMS);

    for (int nq = 0; nq < NQ; nq++) {
        // ---- stage this step's weights into SMEM (padded 12-float rows) ----
        {
            const float4* srcA = reinterpret_cast<const float4*>(g_winT + (size_t)nq * DD * CD);
            const float4* srcB = reinterpret_cast<const float4*>(W_out  + (size_t)nq * DD * CD);
            const float4* srcC = reinterpret_cast<const float4*>(g_cbn  + (size_t)nq * KCB * CD);
#pragma unroll 4
            for (int it = 0; it < 8; it++) {
                int f    = it * NTHREADS + (int)threadIdx.x;
                int half = f >> 10;
                int row  = f & 1023;
                int sidx = row * 2 + half;
                *reinterpret_cast<float4*>(&sWinT[row * 12 + half * 4]) = srcA[sidx];
                *reinterpret_cast<float4*>(&sWout[row * 12 + half * 4]) = srcB[sidx];
                *reinterpret_cast<float4*>(&sCbn [row * 12 + half * 4]) = srcC[sidx];
            }
            reinterpret_cast<float4*>(sBout)[threadIdx.x] =
                reinterpret_cast<const float4*>(b_out + (size_t)nq * DD)[threadIdx.x];
            if (threadIdx.x < 2)
                reinterpret_cast<float4*>(sBin)[threadIdx.x] =
                    reinterpret_cast<const float4*>(b_in + (size_t)nq * CD)[threadIdx.x];
        }
        __syncthreads();

        // ---- in_proj + reduce + bias -> zp (packed channel pairs) ----
        u64t zp[KM][4];
        {
            u64t zeA[KM][4];
#pragma unroll
            for (int j = 0; j < KM; j++)
#pragma unroll
                for (int p = 0; p < 4; p++) zeA[j][p] = 0ull;

#pragma unroll 8
            for (int i = 0; i < 32; i++) {
                int d = lane + 32 * i;
                ulonglong2 wA = *reinterpret_cast<const ulonglong2*>(&sWinT[d * 12]);
                ulonglong2 wB = *reinterpret_cast<const ulonglong2*>(&sWinT[d * 12 + 4]);
#pragma unroll
                for (int j = 0; j < KM; j++) {
                    u64t rd = pk2(r[j][i], r[j][i]);
                    fma2(zeA[j][0], wA.x, rd);
                    fma2(zeA[j][1], wA.y, rd);
                    fma2(zeA[j][2], wB.x, rd);
                    fma2(zeA[j][3], wB.y, rd);
                }
            }

            // packed butterfly reduce (bit-identical per channel)
#pragma unroll
            for (int off = 16; off > 0; off >>= 1) {
#pragma unroll
                for (int j = 0; j < KM; j++)
#pragma unroll
                    for (int p = 0; p < 4; p++)
                        zeA[j][p] = add2(zeA[j][p],
                                         __shfl_xor_sync(0xffffffffu, zeA[j][p], off));
            }

            const ulonglong2* bi = reinterpret_cast<const ulonglong2*>(sBin);
            ulonglong2 b0 = bi[0], b1 = bi[1];
#pragma unroll
            for (int j = 0; j < KM; j++) {
                zp[j][0] = add2(zeA[j][0], b0.x);
                zp[j][1] = add2(zeA[j][1], b0.y);
                zp[j][2] = add2(zeA[j][2], b1.x);
                zp[j][3] = add2(zeA[j][3], b1.y);
            }
        }

        // ---- argmax over dot(ze, cbn_k) ----
        float best[KM];
        int   bk[KM];
#pragma unroll
        for (int j = 0; j < KM; j++) { best[j] = -3.4e38f; bk[j] = 0; }

#pragma unroll 8
        for (int jj = 0; jj < 32; jj++) {
            int k = lane + 32 * jj;
            ulonglong2 cA = *reinterpret_cast<const ulonglong2*>(&sCbn[k * 12]);
            ulonglong2 cB = *reinterpret_cast<const ulonglong2*>(&sCbn[k * 12 + 4]);
#pragma unroll
            for (int j = 0; j < KM; j++) {
                u64t dpp = mul2(zp[j][0], cA.x);
                fma2(dpp, zp[j][1], cA.y);
                fma2(dpp, zp[j][2], cB.x);
                fma2(dpp, zp[j][3], cB.y);
                float2 u = upk2(dpp);
                float dp = u.x + u.y;
                if (dp > best[j]) { best[j] = dp; bk[j] = k; }
            }
        }
#pragma unroll
        for (int off = 16; off > 0; off >>= 1) {
#pragma unroll
            for (int j = 0; j < KM; j++) {
                float ob = __shfl_xor_sync(0xffffffffu, best[j], off);
                int   ok = __shfl_xor_sync(0xffffffffu, bk[j],  off);
                if (ob > best[j] || (ob == best[j] && ok < bk[j])) {
                    best[j] = ob; bk[j] = ok;
                }
            }
        }

        // ---- gather raw codewords (broadcast LDG), negated & mask-scaled ----
        u64t zqn[KM][4];
#pragma unroll
        for (int j = 0; j < KM; j++) {
            const ulonglong2* p = reinterpret_cast<const ulonglong2*>(
                cb + ((size_t)nq * KCB + bk[j]) * CD);
            ulonglong2 qa = __ldg(p);
            ulonglong2 qb = __ldg(p + 1);
            u64t nm = pk2(nmf[j], nmf[j]);
            zqn[j][0] = mul2(qa.x, nm);
            zqn[j][1] = mul2(qa.y, nm);
            zqn[j][2] = mul2(qb.x, nm);
            zqn[j][3] = mul2(qb.y, nm);
        }

        if (lane == 0 && write_idx) {
            float4 iv = make_float4((float)bk[0], (float)bk[1],
                                    (float)bk[2], (float)bk[3]);
            *reinterpret_cast<float4*>(
                &out[QOUT_ELEMS + ((size_t)(nq * BB + b)) * TT + t0]) = iv;
        }

        // ---- out_proj + residual update ----
#pragma unroll 8
        for (int i = 0; i < 32; i++) {
            int d = lane + 32 * i;
            ulonglong2 wA = *reinterpret_cast<const ulonglong2*>(&sWout[d * 12]);
            ulonglong2 wB = *reinterpret_cast<const ulonglong2*>(&sWout[d * 12 + 4]);
            float bo = sBout[d];
#pragma unroll
            for (int j = 0; j < KM; j++) {
                u64t acc = mul2(wA.x, zqn[j][0]);
                fma2(acc, wA.y, zqn[j][1]);
                fma2(acc, wB.x, zqn[j][2]);
                fma2(acc, wB.y, zqn[j][3]);
                float2 u = upk2(acc);
                r[j][i] = fmaf(bo, nmf[j], r[j][i] + (u.x + u.y));
            }
        }
        __syncthreads();
    }

    // ---- qout = (z - r_final) * mask ----
    if (out_size >= QOUT_ELEMS) {
        float* qb = out + ((size_t)b * DD) * TT + t0;
#pragma unroll 8
        for (int i = 0; i < 32; i++) {
            int d = lane + 32 * i;
            float4 v = *reinterpret_cast<const float4*>(zbase + (size_t)d * TT);
            float4 o;
            o.x = (v.x - r[0][i]) * maskf[0];
            o.y = (v.y - r[1][i]) * maskf[1];
            o.z = (v.z - r[2][i]) * maskf[2];
            o.w = (v.w - r[3][i]) * maskf[3];
            *reinterpret_cast<float4*>(qb + (size_t)d * TT) = o;
        }
    }
}

// ---------------------------------------------------------------------------
extern "C" void kernel_launch(void* const* d_in, const int* in_sizes, int n_in,
                              void* d_out, int out_size) {
    const float*     z     = (const float*)d_in[0];
    const long long* len   = (const long long*)d_in[1];
    const float*     W_in  = (const float*)d_in[2];
    const float*     b_in  = (const float*)d_in[3];
    const float*     W_out = (const float*)d_in[4];
    const float*     b_out = (const float*)d_in[5];
    const float*     cbk   = (const float*)d_in[6];
    float* out = (float*)d_out;

    cudaFuncSetAttribute(rvq_kernel,
                         cudaFuncAttributeMaxDynamicSharedMemorySize, SMEM_BYTES);

    rvq_precompute<<<(NQ * DD * CD) / NTHREADS, NTHREADS>>>(W_in, cbk, len, out, out_size);
    rvq_kernel<<<NBLOCKS, NTHREADS, SMEM_BYTES>>>(z, b_in, W_out, b_out, cbk, out, out_size);
}

// round 10
// speedup vs baseline: 1.0517x; 1.0517x over previous
#include <cuda_runtime.h>
#include <cstdint>

#define NQ   32
#define KCB  1024
#define CD   8
#define DD   1024
#define TT   4096
#define BB   8
#define NCOL (BB * TT)

#define QOUT_ELEMS (BB * DD * TT)
#define IDX_ELEMS  (NQ * BB * TT)
#define FULL_OUT   (QOUT_ELEMS + IDX_ELEMS + BB)

typedef unsigned long long u64t;

__device__ __forceinline__ u64t pk2(float a, float b) {
    u64t r; asm("mov.b64 %0,{%1,%2};" : "=l"(r) : "f"(a), "f"(b)); return r;
}
__device__ __forceinline__ float2 upk2(u64t v) {
    float2 r; asm("mov.b64 {%0,%1},%2;" : "=f"(r.x), "=f"(r.y) : "l"(v)); return r;
}
__device__ __forceinline__ void fma2(u64t& d, u64t a, u64t b) {
    asm("fma.rn.f32x2 %0,%1,%2,%0;" : "+l"(d) : "l"(a), "l"(b));
}
__device__ __forceinline__ u64t mul2(u64t a, u64t b) {
    u64t r; asm("mul.rn.f32x2 %0,%1,%2;" : "=l"(r) : "l"(a), "l"(b)); return r;
}

// scratch (device globals; zero-alloc rule)
__device__ float g_ZE0[256 * NCOL];      // [mc][col]
__device__ float g_ZQ [256 * NCOL];      // [mc][col], masked zq
__device__ float g_G  [256 * 256];
__device__ float g_WoT[DD * 256];        // [d][mc]
__device__ float g_cbn[NQ * KCB * CD];
__device__ float g_wboT[NQ * NQ * CD];
__device__ float g_wboCum[NQ * CD];
__device__ float g_bsum[DD];
__device__ int   g_len[BB];

// ---------------- kPre ----------------
__global__ void kPre(const float* __restrict__ W_in, const float* __restrict__ b_in,
                     const float* __restrict__ W_out, const float* __restrict__ b_out,
                     const float* __restrict__ cb, const long long* __restrict__ len64,
                     float* __restrict__ out, int out_size) {
    int tid = blockIdx.x * blockDim.x + threadIdx.x;
    {
        int d = tid >> 8, mc = tid & 255;
        g_WoT[d * 256 + mc] = W_out[((size_t)(mc >> 3) * DD + d) * CD + (mc & 7)];
    }
    if (tid < NQ * KCB) {
        const float* row = cb + (size_t)tid * CD;
        float v[8], n2 = 0.0f;
#pragma unroll
        for (int i = 0; i < 8; i++) { v[i] = row[i]; n2 = fmaf(v[i], v[i], n2); }
        float s = fmaxf(__fsqrt_rn(n2), 1e-12f);
#pragma unroll
        for (int i = 0; i < 8; i++) g_cbn[(size_t)tid * CD + i] = __fdiv_rn(v[i], s);
    }
    if (tid < NQ * NQ * CD) {
        int m = tid >> 8, n = (tid >> 3) & 31, c = tid & 7;
        const float* wr = W_in + ((size_t)m * CD + c) * DD;
        const float* br = b_out + (size_t)n * DD;
        float acc = 0.0f;
        for (int d = 0; d < DD; d++) acc = fmaf(wr[d], br[d], acc);
        g_wboT[tid] = acc;
    }
    if (tid < DD) {
        float s = 0.0f;
        for (int n = 0; n < NQ; n++) s += b_out[(size_t)n * DD + tid];
        g_bsum[tid] = s;
    }
    if (tid == 0) {
        long long tmp[BB]; bool ok = true;
        for (int i = 0; i < BB; i++) { tmp[i] = len64[i]; if (tmp[i] < 0 || tmp[i] > TT) ok = false; }
        if (ok) for (int i = 0; i < BB; i++) g_len[i] = (int)tmp[i];
        else { const int* l = (const int*)len64; for (int i = 0; i < BB; i++) g_len[i] = l[i]; }
        if (out_size >= FULL_OUT)
            for (int i = 0; i < BB; i++) out[QOUT_ELEMS + IDX_ELEMS + i] = (float)g_len[i];
    }
}

// ---------------- kG ----------------
__global__ void kG(const float* __restrict__ W_in) {
    int tid = blockIdx.x * blockDim.x + threadIdx.x;
    int row = tid >> 8, col = tid & 255;
    const float* a = W_in + (size_t)row * DD;
    float acc = 0.0f;
    for (int d = 0; d < DD; d++) acc = fmaf(a[d], g_WoT[d * 256 + col], acc);
    g_G[row * 256 + col] = acc;
    if (tid < NQ * CD) {
        int m = tid >> 3, c = tid & 7;
        float s = 0.0f;
        for (int n = 0; n < m; n++) s += g_wboT[(m * 32 + n) * 8 + c];
        g_wboCum[tid] = s;
    }
}

// ---------------- gemmZE: ZE0 = mask * (Win_all x z) ----------------
__global__ void __launch_bounds__(256)
gemmZE(const float* __restrict__ A, const float* __restrict__ z) {
    __shared__ float As[16 * 64];
    __shared__ float Bs[16 * 136];
    const int tid = threadIdx.x;
    const int bm  = blockIdx.x * 64;
    const int cb0 = blockIdx.y * 128;
    const int b   = cb0 >> 12, t0 = cb0 & 4095;
    const int len = g_len[b];
    const int tx = tid & 15, ty = tid >> 4;
    const float* zb = z + (size_t)b * DD * TT + t0;

    u64t acc[4][4];
#pragma unroll
    for (int i = 0; i < 4; i++)
#pragma unroll
        for (int p = 0; p < 4; p++) acc[i][p] = 0ull;

    for (int kk = 0; kk < 1024; kk += 16) {
        {
            float4 av = *reinterpret_cast<const float4*>(
                A + (size_t)(bm + (tid & 63)) * DD + kk + (tid >> 6) * 4);
            int kb = (tid >> 6) * 4, m = tid & 63;
            As[(kb + 0) * 64 + m] = av.x; As[(kb + 1) * 64 + m] = av.y;
            As[(kb + 2) * 64 + m] = av.z; As[(kb + 3) * 64 + m] = av.w;
#pragma unroll
            for (int it = 0; it < 2; it++) {
                int f = it * 256 + tid, row = f >> 5, c4 = f & 31;
                *reinterpret_cast<float4*>(&Bs[row * 136 + c4 * 4]) =
                    *reinterpret_cast<const float4*>(zb + (size_t)(kk + row) * TT + c4 * 4);
            }
        }
        __syncthreads();
#pragma unroll
        for (int k = 0; k < 16; k++) {
            float4 a4 = *reinterpret_cast<const float4*>(&As[k * 64 + ty * 4]);
            ulonglong2 b0 = *reinterpret_cast<const ulonglong2*>(&Bs[k * 136 + tx * 8]);
            ulonglong2 b1 = *reinterpret_cast<const ulonglong2*>(&Bs[k * 136 + tx * 8 + 4]);
            float aa[4] = {a4.x, a4.y, a4.z, a4.w};
#pragma unroll
            for (int i = 0; i < 4; i++) {
                u64t ap = pk2(aa[i], aa[i]);
                fma2(acc[i][0], ap, b0.x); fma2(acc[i][1], ap, b0.y);
                fma2(acc[i][2], ap, b1.x); fma2(acc[i][3], ap, b1.y);
            }
        }
        __syncthreads();
    }
#pragma unroll
    for (int i = 0; i < 4; i++) {
        int row = bm + ty * 4 + i;
        float* dst = g_ZE0 + (size_t)row * NCOL + cb0 + tx * 8;
#pragma unroll
        for (int p = 0; p < 4; p++) {
            float2 u = upk2(acc[i][p]);
            int tt = t0 + tx * 8 + 2 * p;
            u.x *= (tt < len) ? 1.0f : 0.0f;
            u.y *= (tt + 1 < len) ? 1.0f : 0.0f;
            *reinterpret_cast<float2*>(dst + 2 * p) = u;
        }
    }
}

// ---------------- rvq_scan v2: 4 warps co-scan 32 cols (k-quarters) ----------------
__global__ void __launch_bounds__(256, 2)
rvq_scan(const float* __restrict__ b_in, const float* __restrict__ cb,
         float* __restrict__ out, int out_size) {
    __shared__ float  sCbn[KCB * CD];      // 32 KB
    __shared__ float  sG[64 * 64];         // 16 KB
    __shared__ float2 sArg[8][32];
    const int tid  = threadIdx.x;
    const int lane = tid & 31;
    const int warp = tid >> 5;
    const int grp  = warp >> 2;            // column group 0/1
    const int wq   = warp & 3;             // k quarter
    const int col  = blockIdx.x * 64 + grp * 32 + lane;
    const int b = col >> 12, t = col & 4095;
    const float mask = (t < g_len[b]) ? 1.0f : 0.0f;
    const bool write_idx = (out_size >= QOUT_ELEMS + IDX_ELEMS);

    u64t zqh[32];   // chunk history (this lane's column), fully static indexing

    for (int c = 0; c < 4; c++) {
        __syncthreads();
#pragma unroll
        for (int it = 0; it < 4; it++) {    // stage in-chunk G block [c][c]
            int f = it * 256 + tid, ri = f >> 4, kq = f & 15;
            *reinterpret_cast<float4*>(&sG[ri * 64 + kq * 4]) =
                *reinterpret_cast<const float4*>(&g_G[(c * 64 + ri) * 256 + c * 64 + kq * 4]);
        }
        __syncthreads();

#pragma unroll
        for (int j = 0; j < 8; j++) {
            const int nq = c * 8 + j;
            // stage codebook for this step
#pragma unroll
            for (int it = 0; it < 8; it++) {
                int f = it * 256 + tid;
                *reinterpret_cast<float4*>(&sCbn[f * 4]) =
                    *reinterpret_cast<const float4*>(&g_cbn[(size_t)nq * 8192 + f * 4]);
            }
            __syncthreads();

            // build ze for this lane's column
            float e[8];
#pragma unroll
            for (int cc = 0; cc < 8; cc++)
                e[cc] = g_ZE0[(size_t)(nq * 8 + cc) * NCOL + col]
                      + __ldg(b_in + nq * 8 + cc)
                      - mask * __ldg(g_wboCum + nq * 8 + cc);
#pragma unroll
            for (int jj = 0; jj < j; jj++)
#pragma unroll
                for (int ci = 0; ci < 8; ci++) {
                    const u64t* gp = reinterpret_cast<const u64t*>(
                        &sG[(j * 8 + ci) * 64 + jj * 8]);
                    u64t a = mul2(gp[0], zqh[jj * 4 + 0]);
                    fma2(a, gp[1], zqh[jj * 4 + 1]);
                    fma2(a, gp[2], zqh[jj * 4 + 2]);
                    fma2(a, gp[3], zqh[jj * 4 + 3]);
                    float2 u = upk2(a);
                    e[ci] -= (u.x + u.y);
                }
            u64t zep[4];
#pragma unroll
            for (int p = 0; p < 4; p++) zep[p] = pk2(e[2 * p], e[2 * p + 1]);

            // argmax over this warp's k-quarter (broadcast LDS)
            float best = -3.4e38f; int bk = 0;
            const ulonglong2* cb2 = reinterpret_cast<const ulonglong2*>(sCbn) + wq * 512;
#pragma unroll 4
            for (int kq2 = 0; kq2 < 256; kq2++) {
                ulonglong2 cA = cb2[kq2 * 2], cB = cb2[kq2 * 2 + 1];
                u64t dp = mul2(zep[0], cA.x);
                fma2(dp, zep[1], cA.y);
                fma2(dp, zep[2], cB.x);
                fma2(dp, zep[3], cB.y);
                float2 u = upk2(dp);
                float d = u.x + u.y;
                if (d > best) { best = d; bk = wq * 256 + kq2; }
            }
            sArg[warp][lane] = make_float2(best, __int_as_float(bk));
            __syncthreads();

            // combine quarters in ascending-k order (first-max semantics)
            float2 a0 = sArg[grp * 4 + 0][lane];
            float bb = a0.x; int bki = __float_as_int(a0.y);
#pragma unroll
            for (int q = 1; q < 4; q++) {
                float2 aq = sArg[grp * 4 + q][lane];
                if (aq.x > bb) { bb = aq.x; bki = __float_as_int(aq.y); }
            }

            // gather raw codeword, mask, record history
            const ulonglong2* pcb = reinterpret_cast<const ulonglong2*>(
                cb + ((size_t)nq * KCB + bki) * CD);
            ulonglong2 qa = __ldg(pcb), qb = __ldg(pcb + 1);
            u64t mm = pk2(mask, mask);
            zqh[j * 4 + 0] = mul2(qa.x, mm);
            zqh[j * 4 + 1] = mul2(qa.y, mm);
            zqh[j * 4 + 2] = mul2(qb.x, mm);
            zqh[j * 4 + 3] = mul2(qb.y, mm);

            if (wq == 0) {
#pragma unroll
                for (int p = 0; p < 4; p++) {
                    float2 u = upk2(zqh[j * 4 + p]);
                    g_ZQ[(size_t)(nq * 8 + 2 * p) * NCOL + col] = u.x;
                    g_ZQ[(size_t)(nq * 8 + 2 * p + 1) * NCOL + col] = u.y;
                }
                if (write_idx)
                    out[QOUT_ELEMS + (size_t)(nq * BB + b) * TT + t] = (float)bki;
            }
            __syncthreads();   // sArg reads done before next step overwrites
        }

        // fold chunk into future ZE0 rows (rows split across the 4 warps)
        for (int fc = c + 1; fc < 4; fc++) {
            __syncthreads();
#pragma unroll
            for (int it = 0; it < 4; it++) {
                int f = it * 256 + tid, ri = f >> 4, kq = f & 15;
                *reinterpret_cast<float4*>(&sG[ri * 64 + kq * 4]) =
                    *reinterpret_cast<const float4*>(&g_G[(fc * 64 + ri) * 256 + c * 64 + kq * 4]);
            }
            __syncthreads();
#pragma unroll 4
            for (int r16 = 0; r16 < 16; r16++) {
                int r = wq * 16 + r16;
                const u64t* gp = reinterpret_cast<const u64t*>(&sG[r * 64]);
                u64t a = mul2(gp[0], zqh[0]);
#pragma unroll
                for (int q = 1; q < 32; q++) fma2(a, gp[q], zqh[q]);
                float2 u = upk2(a);
                size_t idx = (size_t)(fc * 64 + r) * NCOL + col;
                g_ZE0[idx] -= (u.x + u.y);
            }
        }
    }
}

// ---------------- gemmQ: qout = WoT x ZQ + mask*bsum ----------------
__global__ void __launch_bounds__(256)
gemmQ(float* __restrict__ out, int out_size) {
    __shared__ float As[16 * 64];
    __shared__ float Bs[16 * 136];
    if (out_size < QOUT_ELEMS) return;
    const int tid = threadIdx.x;
    const int bm  = blockIdx.x * 64;
    const int cb0 = blockIdx.y * 128;
    const int b   = cb0 >> 12, t0 = cb0 & 4095;
    const int len = g_len[b];
    const int tx = tid & 15, ty = tid >> 4;

    u64t acc[4][4];
#pragma unroll
    for (int i = 0; i < 4; i++)
#pragma unroll
        for (int p = 0; p < 4; p++) acc[i][p] = 0ull;

    for (int kk = 0; kk < 256; kk += 16) {
        {
            float4 av = *reinterpret_cast<const float4*>(
                g_WoT + (size_t)(bm + (tid & 63)) * 256 + kk + (tid >> 6) * 4);
            int kb = (tid >> 6) * 4, m = tid & 63;
            As[(kb + 0) * 64 + m] = av.x; As[(kb + 1) * 64 + m] = av.y;
            As[(kb + 2) * 64 + m] = av.z; As[(kb + 3) * 64 + m] = av.w;
#pragma unroll
            for (int it = 0; it < 2; it++) {
                int f = it * 256 + tid, row = f >> 5, c4 = f & 31;
                *reinterpret_cast<float4*>(&Bs[row * 136 + c4 * 4]) =
                    *reinterpret_cast<const float4*>(g_ZQ + (size_t)(kk + row) * NCOL + cb0 + c4 * 4);
            }
        }
        __syncthreads();
#pragma unroll
        for (int k = 0; k < 16; k++) {
            float4 a4 = *reinterpret_cast<const float4*>(&As[k * 64 + ty * 4]);
            ulonglong2 b0 = *reinterpret_cast<const ulonglong2*>(&Bs[k * 136 + tx * 8]);
            ulonglong2 b1 = *reinterpret_cast<const ulonglong2*>(&Bs[k * 136 + tx * 8 + 4]);
            float aa[4] = {a4.x, a4.y, a4.z, a4.w};
#pragma unroll
            for (int i = 0; i < 4; i++) {
                u64t ap = pk2(aa[i], aa[i]);
                fma2(acc[i][0], ap, b0.x); fma2(acc[i][1], ap, b0.y);
                fma2(acc[i][2], ap, b1.x); fma2(acc[i][3], ap, b1.y);
            }
        }
        __syncthreads();
    }
#pragma unroll
    for (int i = 0; i < 4; i++) {
        int d = bm + ty * 4 + i;
        float bs = __ldg(g_bsum + d);
        float* dst = out + (size_t)b * DD * TT + (size_t)d * TT + t0 + tx * 8;
#pragma unroll
        for (int p = 0; p < 4; p++) {
            float2 u = upk2(acc[i][p]);
            int tt = t0 + tx * 8 + 2 * p;
            float m0 = (tt < len) ? 1.0f : 0.0f;
            float m1 = (tt + 1 < len) ? 1.0f : 0.0f;
            u.x += m0 * bs;  u.y += m1 * bs;
            u.x *= m0;       u.y *= m1;
            *reinterpret_cast<float2*>(dst + 2 * p) = u;
        }
    }
}

// ---------------------------------------------------------------------------
extern "C" void kernel_launch(void* const* d_in, const int* in_sizes, int n_in,
                              void* d_out, int out_size) {
    const float*     z     = (const float*)d_in[0];
    const long long* len   = (const long long*)d_in[1];
    const float*     W_in  = (const float*)d_in[2];
    const float*     b_in  = (const float*)d_in[3];
    const float*     W_out = (const float*)d_in[4];
    const float*     b_out = (const float*)d_in[5];
    const float*     cbk   = (const float*)d_in[6];
    float* out = (float*)d_out;

    kPre<<<1024, 256>>>(W_in, b_in, W_out, b_out, cbk, len, out, out_size);
    kG<<<256, 256>>>(W_in);
    gemmZE<<<dim3(4, 256), 256>>>(W_in, z);
    rvq_scan<<<512, 256>>>(b_in, cbk, out, out_size);
    gemmQ<<<dim3(16, 256), 256>>>(out, out_size);
}

// round 12
// speedup vs baseline: 1.0979x; 1.0440x over previous
#include <cuda_runtime.h>
#include <cstdint>

#define NQ   32
#define KCB  1024
#define CD   8
#define DD   1024
#define TT   4096
#define BB   8
#define NCOL (BB * TT)

#define QOUT_ELEMS (BB * DD * TT)
#define IDX_ELEMS  (NQ * BB * TT)
#define FULL_OUT   (QOUT_ELEMS + IDX_ELEMS + BB)

typedef unsigned long long u64t;

__device__ __forceinline__ u64t pk2(float a, float b) {
    u64t r; asm("mov.b64 %0,{%1,%2};" : "=l"(r) : "f"(a), "f"(b)); return r;
}
__device__ __forceinline__ float2 upk2(u64t v) {
    float2 r; asm("mov.b64 {%0,%1},%2;" : "=f"(r.x), "=f"(r.y) : "l"(v)); return r;
}
__device__ __forceinline__ void fma2(u64t& d, u64t a, u64t b) {
    asm("fma.rn.f32x2 %0,%1,%2,%0;" : "+l"(d) : "l"(a), "l"(b));
}
__device__ __forceinline__ u64t mul2(u64t a, u64t b) {
    u64t r; asm("mul.rn.f32x2 %0,%1,%2;" : "=l"(r) : "l"(a), "l"(b)); return r;
}

// scratch (device globals; zero-alloc rule)
__device__ float g_ZE0[256 * NCOL];      // [mc][col]
__device__ float g_ZQ [256 * NCOL];      // [mc][col], masked zq
__device__ float g_G  [256 * 256];
__device__ float g_WoT [DD * 256];       // [d][mc]   (gemmQ A-matrix)
__device__ float g_WoT2[256 * DD];       // [mc][d]   (kG coalesced operand)
__device__ float g_cbn[NQ * KCB * CD];
__device__ float g_wboT[NQ * NQ * CD];
__device__ float g_wboCum[NQ * CD];
__device__ float g_bsum[DD];
__device__ int   g_len[BB];

// ---------------- kPre: transposes, cbn, bsum, len ----------------
__global__ void kPre(const float* __restrict__ W_in, const float* __restrict__ b_in,
                     const float* __restrict__ W_out, const float* __restrict__ b_out,
                     const float* __restrict__ cb, const long long* __restrict__ len64,
                     float* __restrict__ out, int out_size) {
    int tid = blockIdx.x * blockDim.x + threadIdx.x;   // 0..262143
    {
        int d = tid >> 8, mc = tid & 255;
        g_WoT[d * 256 + mc] = W_out[((size_t)(mc >> 3) * DD + d) * CD + (mc & 7)];
    }
    {
        int mc = tid >> 10, d = tid & 1023;
        g_WoT2[tid] = W_out[((size_t)(mc >> 3) * DD + d) * CD + (mc & 7)];
    }
    if (tid < NQ * KCB) {
        const float* row = cb + (size_t)tid * CD;
        float v[8], n2 = 0.0f;
#pragma unroll
        for (int i = 0; i < 8; i++) { v[i] = row[i]; n2 = fmaf(v[i], v[i], n2); }
        float s = fmaxf(__fsqrt_rn(n2), 1e-12f);
#pragma unroll
        for (int i = 0; i < 8; i++) g_cbn[(size_t)tid * CD + i] = __fdiv_rn(v[i], s);
    }
    if (tid < DD) {
        float s = 0.0f;
        for (int n = 0; n < NQ; n++) s += b_out[(size_t)n * DD + tid];
        g_bsum[tid] = s;
    }
    if (tid == 0) {
        long long tmp[BB]; bool ok = true;
        for (int i = 0; i < BB; i++) { tmp[i] = len64[i]; if (tmp[i] < 0 || tmp[i] > TT) ok = false; }
        if (ok) for (int i = 0; i < BB; i++) g_len[i] = (int)tmp[i];
        else { const int* l = (const int*)len64; for (int i = 0; i < BB; i++) g_len[i] = l[i]; }
        if (out_size >= FULL_OUT)
            for (int i = 0; i < BB; i++) out[QOUT_ELEMS + IDX_ELEMS + i] = (float)g_len[i];
    }
}

// ---------------- kWbo: wbo[m][n][c] = W_in^m[c] . b_out^n  (warp per output) ----
__global__ void kWbo(const float* __restrict__ W_in, const float* __restrict__ b_out) {
    int w = (blockIdx.x * blockDim.x + threadIdx.x) >> 5;   // 0..8191
    int lane = threadIdx.x & 31;
    int m = w >> 8, n = (w >> 3) & 31, c = w & 7;
    const float* wr = W_in + ((size_t)m * CD + c) * DD;
    const float* br = b_out + (size_t)n * DD;
    float acc = 0.0f;
#pragma unroll
    for (int i = 0; i < 32; i++)
        acc = fmaf(wr[lane + 32 * i], br[lane + 32 * i], acc);
#pragma unroll
    for (int off = 16; off > 0; off >>= 1)
        acc += __shfl_xor_sync(0xffffffffu, acc, off);
    if (lane == 0) g_wboT[(m * 32 + n) * 8 + c] = acc;
}

// ---------------- kG: G[row][col] = Win[row] . WoT2[col]  (warp per element) ----
__global__ void kG(const float* __restrict__ W_in) {
    int w = (blockIdx.x * blockDim.x + threadIdx.x) >> 5;   // needs 0..65535
    int lane = threadIdx.x & 31;
    int row = w >> 8, col = w & 255;
    const float* a = W_in  + (size_t)row * DD;
    const float* bvec = g_WoT2 + (size_t)col * DD;
    float acc = 0.0f;
#pragma unroll
    for (int i = 0; i < 32; i++)
        acc = fmaf(a[lane + 32 * i], bvec[lane + 32 * i], acc);
#pragma unroll
    for (int off = 16; off > 0; off >>= 1)
        acc += __shfl_xor_sync(0xffffffffu, acc, off);
    if (lane == 0) g_G[row * 256 + col] = acc;

    // wboCum (uses g_wboT from kWbo)
    int t = blockIdx.x * blockDim.x + threadIdx.x;
    if (t < NQ * CD) {
        int m = t >> 3, c = t & 7;
        float s = 0.0f;
        for (int n = 0; n < m; n++) s += g_wboT[(m * 32 + n) * 8 + c];
        g_wboCum[t] = s;
    }
}

// ---------------- gemmZE: ZE0 = mask * (Win_all x z) ----------------
__global__ void __launch_bounds__(256)
gemmZE(const float* __restrict__ A, const float* __restrict__ z) {
    __shared__ float As[16 * 64];
    __shared__ float Bs[16 * 136];
    const int tid = threadIdx.x;
    const int bm  = blockIdx.x * 64;
    const int cb0 = blockIdx.y * 128;
    const int b   = cb0 >> 12, t0 = cb0 & 4095;
    const int len = g_len[b];
    const int tx = tid & 15, ty = tid >> 4;
    const float* zb = z + (size_t)b * DD * TT + t0;

    u64t acc[4][4];
#pragma unroll
    for (int i = 0; i < 4; i++)
#pragma unroll
        for (int p = 0; p < 4; p++) acc[i][p] = 0ull;

    for (int kk = 0; kk < 1024; kk += 16) {
        {
            float4 av = *reinterpret_cast<const float4*>(
                A + (size_t)(bm + (tid & 63)) * DD + kk + (tid >> 6) * 4);
            int kb = (tid >> 6) * 4, m = tid & 63;
            As[(kb + 0) * 64 + m] = av.x; As[(kb + 1) * 64 + m] = av.y;
            As[(kb + 2) * 64 + m] = av.z; As[(kb + 3) * 64 + m] = av.w;
#pragma unroll
            for (int it = 0; it < 2; it++) {
                int f = it * 256 + tid, row = f >> 5, c4 = f & 31;
                *reinterpret_cast<float4*>(&Bs[row * 136 + c4 * 4]) =
                    *reinterpret_cast<const float4*>(zb + (size_t)(kk + row) * TT + c4 * 4);
            }
        }
        __syncthreads();
#pragma unroll
        for (int k = 0; k < 16; k++) {
            float4 a4 = *reinterpret_cast<const float4*>(&As[k * 64 + ty * 4]);
            ulonglong2 b0 = *reinterpret_cast<const ulonglong2*>(&Bs[k * 136 + tx * 8]);
            ulonglong2 b1 = *reinterpret_cast<const ulonglong2*>(&Bs[k * 136 + tx * 8 + 4]);
            float aa[4] = {a4.x, a4.y, a4.z, a4.w};
#pragma unroll
            for (int i = 0; i < 4; i++) {
                u64t ap = pk2(aa[i], aa[i]);
                fma2(acc[i][0], ap, b0.x); fma2(acc[i][1], ap, b0.y);
                fma2(acc[i][2], ap, b1.x); fma2(acc[i][3], ap, b1.y);
            }
        }
        __syncthreads();
    }
#pragma unroll
    for (int i = 0; i < 4; i++) {
        int row = bm + ty * 4 + i;
        float* dst = g_ZE0 + (size_t)row * NCOL + cb0 + tx * 8;
#pragma unroll
        for (int p = 0; p < 4; p++) {
            float2 u = upk2(acc[i][p]);
            int tt = t0 + tx * 8 + 2 * p;
            u.x *= (tt < len) ? 1.0f : 0.0f;
            u.y *= (tt + 1 < len) ? 1.0f : 0.0f;
            *reinterpret_cast<float2*>(dst + 2 * p) = u;
        }
    }
}

// ---------------- rvq_scan v3: double-buffered codebook ----------------
#define SCAN_SMEM_FLOATS (2*8192 + 4096 + 512)
#define SCAN_SMEM_BYTES  (SCAN_SMEM_FLOATS * 4)

__global__ void __launch_bounds__(256, 2)
rvq_scan(const float* __restrict__ b_in, const float* __restrict__ cb,
         float* __restrict__ out, int out_size) {
    extern __shared__ float smem[];
    float*  sCbn = smem;                          // 2 x 8192
    float*  sG   = smem + 2 * 8192;               // 4096
    float2* sArg = (float2*)(smem + 2 * 8192 + 4096);  // [8][32]

    const int tid  = threadIdx.x;
    const int lane = tid & 31;
    const int warp = tid >> 5;
    const int grp  = warp >> 2;
    const int wq   = warp & 3;
    const int col  = blockIdx.x * 64 + grp * 32 + lane;
    const int b = col >> 12, t = col & 4095;
    const float mask = (t < g_len[b]) ? 1.0f : 0.0f;
    const bool write_idx = (out_size >= QOUT_ELEMS + IDX_ELEMS);

    u64t zqh[32];

    // prologue: stage codebook for nq=0 into buf0 (synced by chunk-0 sG sync)
#pragma unroll
    for (int it = 0; it < 8; it++) {
        int f = it * 256 + tid;
        *reinterpret_cast<float4*>(&sCbn[f * 4]) =
            *reinterpret_cast<const float4*>(&g_cbn[f * 4]);
    }

    for (int c = 0; c < 4; c++) {
        __syncthreads();
#pragma unroll
        for (int it = 0; it < 4; it++) {
            int f = it * 256 + tid, ri = f >> 4, kq = f & 15;
            *reinterpret_cast<float4*>(&sG[ri * 64 + kq * 4]) =
                *reinterpret_cast<const float4*>(&g_G[(c * 64 + ri) * 256 + c * 64 + kq * 4]);
        }
        __syncthreads();

#pragma unroll
        for (int j = 0; j < 8; j++) {
            const int nq = c * 8 + j;
            const float* cbCur = sCbn + (nq & 1) * 8192;

            // stage NEXT step's codebook into the other buffer (hidden by argmax)
            if (nq < 31) {
                float* cbNxt = sCbn + ((nq + 1) & 1) * 8192;
#pragma unroll
                for (int it = 0; it < 8; it++) {
                    int f = it * 256 + tid;
                    *reinterpret_cast<float4*>(&cbNxt[f * 4]) =
                        *reinterpret_cast<const float4*>(&g_cbn[(size_t)(nq + 1) * 8192 + f * 4]);
                }
            }

            // build ze for this lane's column
            float e[8];
#pragma unroll
            for (int cc = 0; cc < 8; cc++)
                e[cc] = g_ZE0[(size_t)(nq * 8 + cc) * NCOL + col]
                      + __ldg(b_in + nq * 8 + cc)
                      - mask * __ldg(g_wboCum + nq * 8 + cc);
#pragma unroll
            for (int jj = 0; jj < j; jj++)
#pragma unroll
                for (int ci = 0; ci < 8; ci++) {
                    const u64t* gp = reinterpret_cast<const u64t*>(
                        &sG[(j * 8 + ci) * 64 + jj * 8]);
                    u64t a = mul2(gp[0], zqh[jj * 4 + 0]);
                    fma2(a, gp[1], zqh[jj * 4 + 1]);
                    fma2(a, gp[2], zqh[jj * 4 + 2]);
                    fma2(a, gp[3], zqh[jj * 4 + 3]);
                    float2 u = upk2(a);
                    e[ci] -= (u.x + u.y);
                }
            u64t zep[4];
#pragma unroll
            for (int p = 0; p < 4; p++) zep[p] = pk2(e[2 * p], e[2 * p + 1]);

            // argmax over this warp's k-quarter (broadcast LDS)
            float best = -3.4e38f; int bk = 0;
            const ulonglong2* cb2 = reinterpret_cast<const ulonglong2*>(cbCur) + wq * 512;
#pragma unroll 4
            for (int kq2 = 0; kq2 < 256; kq2++) {
                ulonglong2 cA = cb2[kq2 * 2], cB = cb2[kq2 * 2 + 1];
                u64t dp = mul2(zep[0], cA.x);
                fma2(dp, zep[1], cA.y);
                fma2(dp, zep[2], cB.x);
                fma2(dp, zep[3], cB.y);
                float2 u = upk2(dp);
                float d = u.x + u.y;
                if (d > best) { best = d; bk = wq * 256 + kq2; }
            }
            sArg[warp * 32 + lane] = make_float2(best, __int_as_float(bk));
            __syncthreads();   // covers sArg writes + next-cbn staging

            // combine quarters in ascending-k order (first-max semantics)
            float2 a0 = sArg[(grp * 4 + 0) * 32 + lane];
            float bb = a0.x; int bki = __float_as_int(a0.y);
#pragma unroll
            for (int q = 1; q < 4; q++) {
                float2 aq = sArg[(grp * 4 + q) * 32 + lane];
                if (aq.x > bb) { bb = aq.x; bki = __float_as_int(aq.y); }
            }

            // gather raw codeword, mask, record history
            const ulonglong2* pcb = reinterpret_cast<const ulonglong2*>(
                cb + ((size_t)nq * KCB + bki) * CD);
            ulonglong2 qa = __ldg(pcb), qb = __ldg(pcb + 1);
            u64t mm = pk2(mask, mask);
            zqh[j * 4 + 0] = mul2(qa.x, mm);
            zqh[j * 4 + 1] = mul2(qa.y, mm);
            zqh[j * 4 + 2] = mul2(qb.x, mm);
            zqh[j * 4 + 3] = mul2(qb.y, mm);

            if (wq == 0) {
#pragma unroll
                for (int p = 0; p < 4; p++) {
                    float2 u = upk2(zqh[j * 4 + p]);
                    g_ZQ[(size_t)(nq * 8 + 2 * p) * NCOL + col] = u.x;
                    g_ZQ[(size_t)(nq * 8 + 2 * p + 1) * NCOL + col] = u.y;
                }
                if (write_idx)
                    out[QOUT_ELEMS + (size_t)(nq * BB + b) * TT + t] = (float)bki;
            }
            __syncthreads();   // sArg consumed before next step's writes
        }

        // fold chunk into future ZE0 rows (rows split across the 4 warps)
        for (int fc = c + 1; fc < 4; fc++) {
            __syncthreads();
#pragma unroll
            for (int it = 0; it < 4; it++) {
                int f = it * 256 + tid, ri = f >> 4, kq = f & 15;
                *reinterpret_cast<float4*>(&sG[ri * 64 + kq * 4]) =
                    *reinterpret_cast<const float4*>(&g_G[(fc * 64 + ri) * 256 + c * 64 + kq * 4]);
            }
            __syncthreads();
#pragma unroll 4
            for (int r16 = 0; r16 < 16; r16++) {
                int r = wq * 16 + r16;
                const u64t* gp = reinterpret_cast<const u64t*>(&sG[r * 64]);
                u64t a = mul2(gp[0], zqh[0]);
#pragma unroll
                for (int q = 1; q < 32; q++) fma2(a, gp[q], zqh[q]);
                float2 u = upk2(a);
                size_t idx = (size_t)(fc * 64 + r) * NCOL + col;
                g_ZE0[idx] -= (u.x + u.y);
            }
        }
    }
}

// ---------------- gemmQ: qout = WoT x ZQ + mask*bsum ----------------
__global__ void __launch_bounds__(256)
gemmQ(float* __restrict__ out, int out_size) {
    __shared__ float As[16 * 64];
    __shared__ float Bs[16 * 136];
    if (out_size < QOUT_ELEMS) return;
    const int tid = threadIdx.x;
    const int bm  = blockIdx.x * 64;
    const int cb0 = blockIdx.y * 128;
    const int b   = cb0 >> 12, t0 = cb0 & 4095;
    const int len = g_len[b];
    const int tx = tid & 15, ty = tid >> 4;

    u64t acc[4][4];
#pragma unroll
    for (int i = 0; i < 4; i++)
#pragma unroll
        for (int p = 0; p < 4; p++) acc[i][p] = 0ull;

    for (int kk = 0; kk < 256; kk += 16) {
        {
            float4 av = *reinterpret_cast<const float4*>(
                g_WoT + (size_t)(bm + (tid & 63)) * 256 + kk + (tid >> 6) * 4);
            int kb = (tid >> 6) * 4, m = tid & 63;
            As[(kb + 0) * 64 + m] = av.x; As[(kb + 1) * 64 + m] = av.y;
            As[(kb + 2) * 64 + m] = av.z; As[(kb + 3) * 64 + m] = av.w;
#pragma unroll
            for (int it = 0; it < 2; it++) {
                int f = it * 256 + tid, row = f >> 5, c4 = f & 31;
                *reinterpret_cast<float4*>(&Bs[row * 136 + c4 * 4]) =
                    *reinterpret_cast<const float4*>(g_ZQ + (size_t)(kk + row) * NCOL + cb0 + c4 * 4);
            }
        }
        __syncthreads();
#pragma unroll
        for (int k = 0; k < 16; k++) {
            float4 a4 = *reinterpret_cast<const float4*>(&As[k * 64 + ty * 4]);
            ulonglong2 b0 = *reinterpret_cast<const ulonglong2*>(&Bs[k * 136 + tx * 8]);
            ulonglong2 b1 = *reinterpret_cast<const ulonglong2*>(&Bs[k * 136 + tx * 8 + 4]);
            float aa[4] = {a4.x, a4.y, a4.z, a4.w};
#pragma unroll
            for (int i = 0; i < 4; i++) {
                u64t ap = pk2(aa[i], aa[i]);
                fma2(acc[i][0], ap, b0.x); fma2(acc[i][1], ap, b0.y);
                fma2(acc[i][2], ap, b1.x); fma2(acc[i][3], ap, b1.y);
            }
        }
        __syncthreads();
    }
#pragma unroll
    for (int i = 0; i < 4; i++) {
        int d = bm + ty * 4 + i;
        float bs = __ldg(g_bsum + d);
        float* dst = out + (size_t)b * DD * TT + (size_t)d * TT + t0 + tx * 8;
#pragma unroll
        for (int p = 0; p < 4; p++) {
            float2 u = upk2(acc[i][p]);
            int tt = t0 + tx * 8 + 2 * p;
            float m0 = (tt < len) ? 1.0f : 0.0f;
            float m1 = (tt + 1 < len) ? 1.0f : 0.0f;
            u.x += m0 * bs;  u.y += m1 * bs;
            u.x *= m0;       u.y *= m1;
            *reinterpret_cast<float2*>(dst + 2 * p) = u;
        }
    }
}

// ---------------------------------------------------------------------------
extern "C" void kernel_launch(void* const* d_in, const int* in_sizes, int n_in,
                              void* d_out, int out_size) {
    const float*     z     = (const float*)d_in[0];
    const long long* len   = (const long long*)d_in[1];
    const float*     W_in  = (const float*)d_in[2];
    const float*     b_in  = (const float*)d_in[3];
    const float*     W_out = (const float*)d_in[4];
    const float*     b_out = (const float*)d_in[5];
    const float*     cbk   = (const float*)d_in[6];
    float* out = (float*)d_out;

    cudaFuncSetAttribute(rvq_scan,
                         cudaFuncAttributeMaxDynamicSharedMemorySize, SCAN_SMEM_BYTES);

    kPre<<<1024, 256>>>(W_in, b_in, W_out, b_out, cbk, len, out, out_size);
    kWbo<<<1024, 256>>>(W_in, b_out);
    kG<<<8192, 256>>>(W_in);   // FIX: 65536 warp-outputs need 8192 blocks (was 2048)
    gemmZE<<<dim3(4, 256), 256>>>(W_in, z);
    rvq_scan<<<512, 256, SCAN_SMEM_BYTES>>>(b_in, cbk, out, out_size);
    gemmQ<<<dim3(16, 256), 256>>>(out, out_size);
}